// round 2
// baseline (speedup 1.0000x reference)
#include <cuda_runtime.h>

// Bidirectional GRU, persistent-kernel formulation.
// T=512, B=64, I=H=512. 128 blocks (2 dirs x 64 column-blocks of 8 h-columns),
// 256 threads (128 compute lanes x 2-way k-split). Weights resident in smem.
// Per-timestep software grid barrier; h history stored in d_out itself.

#define T_STEPS 512
#define BATCH   64
#define HID     512
#define NBLK    128
#define THREADS 256

// out layout: [T][B][2H] floats, then hT_f [B][H], then hT_b [B][H]
#define OUT_ROW   1024            // 2H
#define OUT_TSTR  (BATCH * OUT_ROW)

__device__ unsigned g_count = 0;
__device__ unsigned g_gen   = 0;

__device__ __forceinline__ float sigmoidf_(float x) {
    return 1.0f / (1.0f + __expf(-x));
}

__device__ __forceinline__ void grid_barrier() {
    __syncthreads();
    if (threadIdx.x == 0) {
        volatile unsigned* vgen = &g_gen;
        unsigned gen = *vgen;
        unsigned ticket = atomicAdd(&g_count, 1u);
        if (ticket == NBLK - 1u) {
            atomicExch(&g_count, 0u);
            __threadfence();
            atomicAdd(&g_gen, 1u);   // release
        } else {
            while (*vgen == gen) { __nanosleep(32); }
        }
    }
    __syncthreads();
}

extern "C" __global__ void __launch_bounds__(THREADS, 1)
gru_bidir_kernel(const float* __restrict__ inp,
                 const float* __restrict__ h0f,  const float* __restrict__ h0b,
                 const float* __restrict__ Wih_f, const float* __restrict__ Whh_f,
                 const float* __restrict__ bih_f, const float* __restrict__ bhh_f,
                 const float* __restrict__ Wih_b, const float* __restrict__ Whh_b,
                 const float* __restrict__ bih_b, const float* __restrict__ bhh_b,
                 float* __restrict__ out)
{
    extern __shared__ float smem[];     // [6][8][512] weights, then red[128][17]
    const int tid  = threadIdx.x;
    const int dir  = blockIdx.x >> 6;   // 0 = fwd, 1 = bwd
    const int jblk = blockIdx.x & 63;
    const int j0   = jblk * 8;

    const float* Wih = dir ? Wih_b : Wih_f;
    const float* Whh = dir ? Whh_b : Whh_f;
    const float* bih = dir ? bih_b : bih_f;
    const float* bhh = dir ? bhh_b : bhh_f;
    const float* h0  = dir ? h0b   : h0f;

    // ---- Load weight slices to shared: 6 sets x 8 rows x 512 cols ----
    // set 0..2: Wih gates r,z,n ; set 3..5: Whh gates r,z,n
    for (int i = tid; i < 6144; i += THREADS) {           // 6144 float4s
        int row = i >> 7;         // 0..47
        int c4  = i & 127;
        int set = row >> 3;
        int jj  = row & 7;
        const float* W = (set < 3) ? Wih : Whh;
        int g = (set < 3) ? set : (set - 3);
        ((float4*)smem)[i] =
            ((const float4*)(W + ((size_t)(g * HID + j0 + jj) << 9)))[c4];
    }
    float* red = smem + 6 * 8 * 512;    // 128 * 17 floats, padded for banks

    const int ktid  = tid >> 7;         // k-split half: 0 or 1
    const int lt    = tid & 127;        // compute lane
    const int j_idx = lt >> 4;          // 0..7
    const int b0    = (lt & 15) * 4;    // 4 batch rows per lane
    const int j     = j0 + j_idx;

    // biases in registers (constant across steps)
    const float bR  = bih[j]           + bhh[j];
    const float bZ  = bih[HID + j]     + bhh[HID + j];
    const float bIN = bih[2 * HID + j];
    const float bHN = bhh[2 * HID + j];

    const float* wIr = smem + (0 * 8 + j_idx) * 512;
    const float* wIz = smem + (1 * 8 + j_idx) * 512;
    const float* wIn = smem + (2 * 8 + j_idx) * 512;
    const float* wHr = smem + (3 * 8 + j_idx) * 512;
    const float* wHz = smem + (4 * 8 + j_idx) * 512;
    const float* wHn = smem + (5 * 8 + j_idx) * 512;

    float* hT_out = out + (size_t)T_STEPS * OUT_TSTR + (size_t)dir * (BATCH * HID);

    __syncthreads();

    const int kbeg = ktid * 256;

    for (int s = 0; s < T_STEPS; ++s) {
        const int t = dir ? (T_STEPS - 1 - s) : s;
        const float* xrow = inp + ((size_t)t * BATCH + b0) * 512;
        const float* hrow;
        int hstr;
        if (s == 0) {
            hrow = h0 + (size_t)b0 * HID;  hstr = HID;
        } else {
            const int tp = dir ? (t + 1) : (t - 1);
            hrow = out + (size_t)tp * OUT_TSTR + (size_t)b0 * OUT_ROW + dir * HID;
            hstr = OUT_ROW;
        }

        float aR[4]  = {0.f, 0.f, 0.f, 0.f};
        float aZ[4]  = {0.f, 0.f, 0.f, 0.f};
        float aIN[4] = {0.f, 0.f, 0.f, 0.f};
        float aHN[4] = {0.f, 0.f, 0.f, 0.f};

        #pragma unroll 2
        for (int k = kbeg; k < kbeg + 256; k += 4) {
            const float4 vIr = *(const float4*)(wIr + k);
            const float4 vIz = *(const float4*)(wIz + k);
            const float4 vIn = *(const float4*)(wIn + k);
            const float4 vHr = *(const float4*)(wHr + k);
            const float4 vHz = *(const float4*)(wHz + k);
            const float4 vHn = *(const float4*)(wHn + k);
            #pragma unroll
            for (int bb = 0; bb < 4; ++bb) {
                const float4 xv = __ldg((const float4*)(xrow + bb * 512 + k));
                const float4 hv = __ldg((const float4*)(hrow + bb * hstr + k));
                aR[bb]  = fmaf(xv.x, vIr.x, aR[bb]);
                aR[bb]  = fmaf(hv.x, vHr.x, aR[bb]);
                aZ[bb]  = fmaf(xv.x, vIz.x, aZ[bb]);
                aZ[bb]  = fmaf(hv.x, vHz.x, aZ[bb]);
                aIN[bb] = fmaf(xv.x, vIn.x, aIN[bb]);
                aHN[bb] = fmaf(hv.x, vHn.x, aHN[bb]);

                aR[bb]  = fmaf(xv.y, vIr.y, aR[bb]);
                aR[bb]  = fmaf(hv.y, vHr.y, aR[bb]);
                aZ[bb]  = fmaf(xv.y, vIz.y, aZ[bb]);
                aZ[bb]  = fmaf(hv.y, vHz.y, aZ[bb]);
                aIN[bb] = fmaf(xv.y, vIn.y, aIN[bb]);
                aHN[bb] = fmaf(hv.y, vHn.y, aHN[bb]);

                aR[bb]  = fmaf(xv.z, vIr.z, aR[bb]);
                aR[bb]  = fmaf(hv.z, vHr.z, aR[bb]);
                aZ[bb]  = fmaf(xv.z, vIz.z, aZ[bb]);
                aZ[bb]  = fmaf(hv.z, vHz.z, aZ[bb]);
                aIN[bb] = fmaf(xv.z, vIn.z, aIN[bb]);
                aHN[bb] = fmaf(hv.z, vHn.z, aHN[bb]);

                aR[bb]  = fmaf(xv.w, vIr.w, aR[bb]);
                aR[bb]  = fmaf(hv.w, vHr.w, aR[bb]);
                aZ[bb]  = fmaf(xv.w, vIz.w, aZ[bb]);
                aZ[bb]  = fmaf(hv.w, vHz.w, aZ[bb]);
                aIN[bb] = fmaf(xv.w, vIn.w, aIN[bb]);
                aHN[bb] = fmaf(hv.w, vHn.w, aHN[bb]);
            }
        }

        // ---- k-split reduction ----
        if (ktid == 1) {
            float* rr = red + lt * 17;
            #pragma unroll
            for (int bb = 0; bb < 4; ++bb) {
                rr[bb]      = aR[bb];
                rr[4 + bb]  = aZ[bb];
                rr[8 + bb]  = aIN[bb];
                rr[12 + bb] = aHN[bb];
            }
        }
        __syncthreads();

        if (ktid == 0) {
            const float* rr = red + lt * 17;
            #pragma unroll
            for (int bb = 0; bb < 4; ++bb) {
                const float sR  = aR[bb]  + rr[bb]      + bR;
                const float sZ  = aZ[bb]  + rr[4 + bb]  + bZ;
                const float sIN = aIN[bb] + rr[8 + bb]  + bIN;
                const float sHN = aHN[bb] + rr[12 + bb] + bHN;
                const float r = sigmoidf_(sR);
                const float z = sigmoidf_(sZ);
                const float n = tanhf(sIN + r * sHN);
                const float hp = __ldg(hrow + bb * hstr + j);
                const float hn = (1.0f - z) * n + z * hp;
                out[(size_t)t * OUT_TSTR + (size_t)(b0 + bb) * OUT_ROW + dir * HID + j] = hn;
                if (s == T_STEPS - 1)
                    hT_out[(size_t)(b0 + bb) * HID + j] = hn;
            }
        }

        // Publish h writes to L2 AND invalidate this SM's L1 (CCTL.IVALL) so
        // next step's __ldg reads are coherent across blocks.
        __threadfence();
        grid_barrier();
    }
}

extern "C" void kernel_launch(void* const* d_in, const int* in_sizes, int n_in,
                              void* d_out, int out_size)
{
    (void)in_sizes; (void)n_in; (void)out_size;
    const float* inp   = (const float*)d_in[0];
    const float* h0f   = (const float*)d_in[1];
    const float* h0b   = (const float*)d_in[2];
    const float* Wih_f = (const float*)d_in[3];
    const float* Whh_f = (const float*)d_in[4];
    const float* bih_f = (const float*)d_in[5];
    const float* bhh_f = (const float*)d_in[6];
    const float* Wih_b = (const float*)d_in[7];
    const float* Whh_b = (const float*)d_in[8];
    const float* bih_b = (const float*)d_in[9];
    const float* bhh_b = (const float*)d_in[10];
    float* out = (float*)d_out;

    const size_t smem_bytes = (6 * 8 * 512 + 128 * 17) * sizeof(float); // 106,944 B
    cudaFuncSetAttribute(gru_bidir_kernel,
                         cudaFuncAttributeMaxDynamicSharedMemorySize,
                         (int)smem_bytes);

    gru_bidir_kernel<<<NBLK, THREADS, smem_bytes>>>(
        inp, h0f, h0b,
        Wih_f, Whh_f, bih_f, bhh_f,
        Wih_b, Whh_b, bih_b, bhh_b,
        out);
}

// round 5
// speedup vs baseline: 3.3663x; 3.3663x over previous
#include <cuda_runtime.h>

// Bidirectional GRU, persistent kernel, round 3.
// 128 blocks = 2 dirs x 64 j-blocks (8 h-columns each), 256 threads.
// Thread = (b, j-pair): b = tid & 63, jp = tid >> 6  -> 2 h-columns per thread.
// Warp = 32 consecutive b, same j-pair  => weight LDS are warp-broadcast.
// x(t) and h(t-1) staged into padded smem per 128-k chunk (coalesced LDG).
// Dot products use packed fma.rn.f32x2 (FFMA2).

#define T_STEPS 512
#define BATCH   64
#define HID     512
#define NBLK    128
#define THREADS 256
#define PAD_ROW 132              // 128 + 4 floats pad: 16B aligned, conflict-free

#define OUT_ROW   1024           // 2H
#define OUT_TSTR  (BATCH * OUT_ROW)

__device__ unsigned g_count = 0;
__device__ unsigned g_gen   = 0;

__device__ __forceinline__ float sigmoidf_(float x) {
    return 1.0f / (1.0f + __expf(-x));
}

__device__ __forceinline__ void fma2(unsigned long long& d,
                                     unsigned long long a,
                                     unsigned long long b) {
    asm volatile("fma.rn.f32x2 %0, %1, %2, %0;" : "+l"(d) : "l"(a), "l"(b));
}

__device__ __forceinline__ float2 unpk(unsigned long long v) {
    float2 r;
    asm("mov.b64 {%0,%1}, %2;" : "=f"(r.x), "=f"(r.y) : "l"(v));
    return r;
}

__device__ __forceinline__ void grid_barrier() {
    __syncthreads();
    if (threadIdx.x == 0) {
        volatile unsigned* vgen = &g_gen;
        unsigned gen = *vgen;
        unsigned ticket = atomicAdd(&g_count, 1u);
        if (ticket == NBLK - 1u) {
            atomicExch(&g_count, 0u);
            __threadfence();
            atomicAdd(&g_gen, 1u);   // release
        } else {
            while (*vgen == gen) { __nanosleep(32); }
        }
    }
    __syncthreads();
}

extern "C" __global__ void __launch_bounds__(THREADS, 1)
gru_bidir_kernel(const float* __restrict__ inp,
                 const float* __restrict__ h0f,  const float* __restrict__ h0b,
                 const float* __restrict__ Wih_f, const float* __restrict__ Whh_f,
                 const float* __restrict__ bih_f, const float* __restrict__ bhh_f,
                 const float* __restrict__ Wih_b, const float* __restrict__ Whh_b,
                 const float* __restrict__ bih_b, const float* __restrict__ bhh_b,
                 float* __restrict__ out)
{
    extern __shared__ float smem[];
    float* ws = smem;                       // [6][8][512] weights = 24576 floats
    float* xs = smem + 6 * 8 * 512;         // [64][PAD_ROW]
    float* hs = xs + BATCH * PAD_ROW;       // [64][PAD_ROW]

    const int tid  = threadIdx.x;
    const int dir  = blockIdx.x >> 6;       // 0 = fwd, 1 = bwd
    const int jblk = blockIdx.x & 63;
    const int j0   = jblk * 8;

    const float* Wih = dir ? Wih_b : Wih_f;
    const float* Whh = dir ? Whh_b : Whh_f;
    const float* bih = dir ? bih_b : bih_f;
    const float* bhh = dir ? bhh_b : bhh_f;
    const float* h0  = dir ? h0b   : h0f;

    // ---- Weights to shared: set 0..2 = Wih(r,z,n), 3..5 = Whh(r,z,n) ----
    for (int i = tid; i < 6144; i += THREADS) {       // 6144 float4s
        int row = i >> 7;       // 0..47
        int c4  = i & 127;
        int set = row >> 3;
        int jj  = row & 7;
        const float* W = (set < 3) ? Wih : Whh;
        int g = (set < 3) ? set : (set - 3);
        ((float4*)ws)[i] =
            ((const float4*)(W + ((size_t)(g * HID + j0 + jj) << 9)))[c4];
    }

    const int b  = tid & 63;
    const int jp = tid >> 6;                // 0..3, same across a warp
    const int jA = j0 + jp * 2;             // first of this thread's 2 columns
    const int jchunk = j0 >> 7;             // which 128-k chunk holds column j
    const int j_in   = jA & 127;

    // weight row pointers (per jj in {0,1}); order: Ir,Iz,In,Hr,Hz,Hn
    const float* wp[12];
    #pragma unroll
    for (int set = 0; set < 6; ++set)
        #pragma unroll
        for (int jj = 0; jj < 2; ++jj)
            wp[set * 2 + jj] = ws + ((set * 8 + jp * 2 + jj) << 9);

    // biases for 2 columns
    float bR[2], bZ[2], bIN[2], bHN[2];
    #pragma unroll
    for (int jj = 0; jj < 2; ++jj) {
        int j = jA + jj;
        bR[jj]  = bih[j]           + bhh[j];
        bZ[jj]  = bih[HID + j]     + bhh[HID + j];
        bIN[jj] = bih[2 * HID + j];
        bHN[jj] = bhh[2 * HID + j];
    }

    float* hT_out = out + (size_t)T_STEPS * OUT_TSTR + (size_t)dir * (BATCH * HID);

    __syncthreads();

    for (int s = 0; s < T_STEPS; ++s) {
        const int t  = dir ? (T_STEPS - 1 - s) : s;
        const int tp = dir ? (t + 1) : (t - 1);

        const float* hgbase;
        int hstr;
        if (s == 0) { hgbase = h0;                                    hstr = HID; }
        else        { hgbase = out + (size_t)tp * OUT_TSTR + dir * HID; hstr = OUT_ROW; }

        unsigned long long aR[2]  = {0ull, 0ull};
        unsigned long long aZ[2]  = {0ull, 0ull};
        unsigned long long aIN[2] = {0ull, 0ull};
        unsigned long long aHN[2] = {0ull, 0ull};
        float hp[2];

        for (int c = 0; c < 4; ++c) {
            const int kb = c * 128;
            // ---- stage x[64][kb..kb+128) and h_prev[64][kb..kb+128) ----
            const float* xg = inp + (size_t)t * (BATCH * 512) + kb;
            const float* hg = hgbase + kb;
            #pragma unroll
            for (int i = 0; i < 8; ++i) {
                int idx = tid + i * THREADS;      // 0..2047
                int bb  = idx >> 5;
                int c4  = idx & 31;
                float4 xv4 = __ldg((const float4*)(xg + (size_t)bb * 512) + c4);
                *(float4*)(xs + bb * PAD_ROW + c4 * 4) = xv4;
                float4 hv4 = __ldg((const float4*)(hg + (size_t)bb * hstr) + c4);
                *(float4*)(hs + bb * PAD_ROW + c4 * 4) = hv4;
            }
            __syncthreads();

            if (c == jchunk) {
                hp[0] = hs[b * PAD_ROW + j_in];
                hp[1] = hs[b * PAD_ROW + j_in + 1];
            }

            const float* xrow = xs + b * PAD_ROW;
            const float* hrow = hs + b * PAD_ROW;

            #pragma unroll 2
            for (int kk = 0; kk < 128; kk += 4) {
                const ulonglong2 xv = *(const ulonglong2*)(xrow + kk);
                const ulonglong2 hv = *(const ulonglong2*)(hrow + kk);
                const int k = kb + kk;
                #pragma unroll
                for (int jj = 0; jj < 2; ++jj) {
                    const ulonglong2 wIr = *(const ulonglong2*)(wp[0 + jj] + k);
                    const ulonglong2 wIz = *(const ulonglong2*)(wp[2 + jj] + k);
                    const ulonglong2 wIn = *(const ulonglong2*)(wp[4 + jj] + k);
                    const ulonglong2 wHr = *(const ulonglong2*)(wp[6 + jj] + k);
                    const ulonglong2 wHz = *(const ulonglong2*)(wp[8 + jj] + k);
                    const ulonglong2 wHn = *(const ulonglong2*)(wp[10 + jj] + k);
                    fma2(aR[jj],  xv.x, wIr.x);  fma2(aR[jj],  xv.y, wIr.y);
                    fma2(aR[jj],  hv.x, wHr.x);  fma2(aR[jj],  hv.y, wHr.y);
                    fma2(aZ[jj],  xv.x, wIz.x);  fma2(aZ[jj],  xv.y, wIz.y);
                    fma2(aZ[jj],  hv.x, wHz.x);  fma2(aZ[jj],  hv.y, wHz.y);
                    fma2(aIN[jj], xv.x, wIn.x);  fma2(aIN[jj], xv.y, wIn.y);
                    fma2(aHN[jj], hv.x, wHn.x);  fma2(aHN[jj], hv.y, wHn.y);
                }
            }
            __syncthreads();   // before next chunk overwrites xs/hs
        }

        // ---- gates + output for this thread's (b, 2 columns) ----
        float hn[2];
        #pragma unroll
        for (int jj = 0; jj < 2; ++jj) {
            const float2 r2  = unpk(aR[jj]);
            const float2 z2  = unpk(aZ[jj]);
            const float2 in2 = unpk(aIN[jj]);
            const float2 hn2 = unpk(aHN[jj]);
            const float sR  = r2.x  + r2.y  + bR[jj];
            const float sZ  = z2.x  + z2.y  + bZ[jj];
            const float sIN = in2.x + in2.y + bIN[jj];
            const float sHN = hn2.x + hn2.y + bHN[jj];
            const float r = sigmoidf_(sR);
            const float z = sigmoidf_(sZ);
            const float n = tanhf(sIN + r * sHN);
            hn[jj] = (1.0f - z) * n + z * hp[jj];
        }
        *(float2*)(out + (size_t)t * OUT_TSTR + (size_t)b * OUT_ROW + dir * HID + jA)
            = make_float2(hn[0], hn[1]);
        if (s == T_STEPS - 1)
            *(float2*)(hT_out + (size_t)b * HID + jA) = make_float2(hn[0], hn[1]);

        // publish h to L2 + invalidate L1 (CCTL.IVALL), then grid barrier
        __threadfence();
        grid_barrier();
    }
}

extern "C" void kernel_launch(void* const* d_in, const int* in_sizes, int n_in,
                              void* d_out, int out_size)
{
    (void)in_sizes; (void)n_in; (void)out_size;
    const float* inp   = (const float*)d_in[0];
    const float* h0f   = (const float*)d_in[1];
    const float* h0b   = (const float*)d_in[2];
    const float* Wih_f = (const float*)d_in[3];
    const float* Whh_f = (const float*)d_in[4];
    const float* bih_f = (const float*)d_in[5];
    const float* bhh_f = (const float*)d_in[6];
    const float* Wih_b = (const float*)d_in[7];
    const float* Whh_b = (const float*)d_in[8];
    const float* bih_b = (const float*)d_in[9];
    const float* bhh_b = (const float*)d_in[10];
    float* out = (float*)d_out;

    const size_t smem_bytes =
        (6 * 8 * 512 + 2 * BATCH * PAD_ROW) * sizeof(float);   // 165,888 B
    cudaFuncSetAttribute(gru_bidir_kernel,
                         cudaFuncAttributeMaxDynamicSharedMemorySize,
                         (int)smem_bytes);

    gru_bidir_kernel<<<NBLK, THREADS, smem_bytes>>>(
        inp, h0f, h0b,
        Wih_f, Whh_f, bih_f, bhh_f,
        Wih_b, Whh_b, bih_b, bhh_b,
        out);
}